// round 15
// baseline (speedup 1.0000x reference)
#include <cuda_runtime.h>
#include <cuda_fp16.h>
#include <cstdint>

#define NROWS  4096
#define DMODEL 512
#define DK     64
#define ND     (NROWS * DMODEL)
#define DD     (DMODEL * DMODEL)

// Packed, pre-swizzled tile images (exact smem layout, bulk-TMA contiguous):
//  X pack: [z][mblk(32)][chunk(8)] -> 128 rows x 128B image (16KB)
//  W pack: [z][nblk(8)][chunk(8)]  -> 64 rows x 128B image  (8KB)
//  Y pack: [mblk(32)][chunk(8)]    -> 16KB images (attention output)
#define XPACK_Z (32 * 8 * 16384)
#define WPACK_Z (8 * 8 * 8192)

__device__ __align__(128) char  g_xpack[3 * XPACK_Z];
__device__ __align__(128) char  g_wpack[4 * WPACK_Z];
__device__ __align__(128) char  g_ypack[XPACK_Z];
__device__ __half g_qkv[3][ND];          // fp16 Q/K/V (plain row-major)

// ---------------- PTX helpers ----------------
static __device__ __forceinline__ uint32_t s2u(const void* p) {
    uint32_t a;
    asm("{ .reg .u64 t; cvta.to.shared.u64 t, %1; cvt.u32.u64 %0, t; }" : "=r"(a) : "l"(p));
    return a;
}
static __device__ __forceinline__ void ldsm4(uint32_t& r0, uint32_t& r1, uint32_t& r2,
                                             uint32_t& r3, uint32_t a) {
    asm volatile("ldmatrix.sync.aligned.m8n8.x4.shared.b16 {%0,%1,%2,%3}, [%4];"
                 : "=r"(r0), "=r"(r1), "=r"(r2), "=r"(r3) : "r"(a));
}
static __device__ __forceinline__ void mma_f16(float* c, const uint32_t* a, const uint32_t* b) {
    asm volatile(
        "mma.sync.aligned.m16n8k16.row.col.f32.f16.f16.f32 "
        "{%0,%1,%2,%3}, {%4,%5,%6,%7}, {%8,%9}, {%0,%1,%2,%3};"
        : "+f"(c[0]), "+f"(c[1]), "+f"(c[2]), "+f"(c[3])
        : "r"(a[0]), "r"(a[1]), "r"(a[2]), "r"(a[3]), "r"(b[0]), "r"(b[1]));
}
static __device__ __forceinline__ void bar_init(uint32_t a, uint32_t c) {
    asm volatile("mbarrier.init.shared.b64 [%0], %1;" :: "r"(a), "r"(c) : "memory");
}
static __device__ __forceinline__ void bar_expect_tx(uint32_t a, uint32_t tx) {
    asm volatile("mbarrier.arrive.expect_tx.shared.b64 _, [%0], %1;" :: "r"(a), "r"(tx) : "memory");
}
static __device__ __forceinline__ void bulk_g2s(uint32_t dst, const void* src,
                                                uint32_t bytes, uint32_t bar) {
    asm volatile(
        "cp.async.bulk.shared::cluster.global.mbarrier::complete_tx::bytes [%0], [%1], %2, [%3];"
        :: "r"(dst), "l"(src), "r"(bytes), "r"(bar) : "memory");
}
static __device__ __forceinline__ void bar_wait(uint32_t a, uint32_t parity) {
    uint32_t done;
    asm volatile(
        "{\n\t.reg .pred p;\n\t"
        "mbarrier.try_wait.parity.acquire.cta.shared::cta.b64 p, [%1], %2;\n\t"
        "selp.b32 %0, 1, 0, p;\n\t}"
        : "=r"(done) : "r"(a), "r"(parity) : "memory");
    if (!done) {
        asm volatile(
            "{\n\t.reg .pred P1;\n\t"
            "WL_%=:\n\t"
            "mbarrier.try_wait.parity.acquire.cta.shared::cta.b64 P1, [%0], %1, 0x989680;\n\t"
            "@P1 bra.uni WD_%=;\n\t"
            "bra.uni WL_%=;\n\t"
            "WD_%=:\n\t}"
            :: "r"(a), "r"(parity) : "memory");
    }
}
#define SWZ(x) ((x) ^ (((x) >> 3) & 0x70))

struct GemmPtrs {
    const char*  Ap[3];
    const char*  Bp[3];
    const float* bias[3];
    void*        C[3];
};

// ---------------- FAT GEMM: CTA tile 128x128, DOUBLE-BANKED accumulators -----
// 8 warps as 2m x 4n, warp tile 64x32. Even/odd t-steps accumulate into
// separate banks -> accumulator RAW chain halves (32 -> 16 steps of ~600cyc
// HMMA latency). acc = 128 regs -> 1 CTA/SM (255-reg budget).
#define FAT_STAGE 32768
#define FAT_GSMEM (3 * FAT_STAGE + 64)

template <typename OutT>
__global__ __launch_bounds__(256, 1)
void gemm_fat_f16(GemmPtrs p)
{
    extern __shared__ char smem[];
    const uint32_t sb = s2u(smem);
    const uint32_t barB = sb + 3 * FAT_STAGE;
    const int z = blockIdx.z;
    const char* __restrict__ Ap = p.Ap[z];
    const char* __restrict__ Bp = p.Bp[z];
    const float* __restrict__ bias = p.bias[z];
    OutT* __restrict__ C = (OutT*)p.C[z];

    const int tid = threadIdx.x, wid = tid >> 5, lane = tid & 31;
    const int mblk = blockIdx.y, jn = blockIdx.x;
    const int m0 = mblk << 7, n0 = jn << 7;
    const int wm = wid & 1, wn = wid >> 1;

    const int a_row   = (wm << 6) + (lane & 15);
    const int a_kh    = lane >> 4;
    const int b_lrow0 = ((wn & 1) << 5) + (((lane >> 4) & 1) << 3) + (lane & 7);
    const int b_kh    = (lane >> 3) & 1;
    const int bimg    = wn >> 1;

    float acc[2][4][4][4];    // [bank][mi][ni][r]
    #pragma unroll
    for (int bk = 0; bk < 2; bk++)
        #pragma unroll
        for (int i = 0; i < 4; i++)
            #pragma unroll
            for (int j = 0; j < 4; j++)
                #pragma unroll
                for (int r = 0; r < 4; r++) acc[bk][i][j][r] = 0.f;

    if (tid == 0) {
        #pragma unroll
        for (int s = 0; s < 3; s++) bar_init(barB + (s << 3), 1);
        asm volatile("fence.proxy.async.shared::cta;" ::: "memory");
    }
    __syncthreads();

    auto issue = [&](int chunk, int st) {
        const uint32_t bar = barB + (st << 3);
        bar_expect_tx(bar, FAT_STAGE);
        bulk_g2s(sb + st * FAT_STAGE,
                 Ap + (((size_t)mblk << 3) + chunk) * 16384, 16384, bar);
        bulk_g2s(sb + st * FAT_STAGE + 16384,
                 Bp + ((((size_t)jn << 1) << 3) + chunk) * 8192, 8192, bar);
        bulk_g2s(sb + st * FAT_STAGE + 24576,
                 Bp + (((((size_t)jn << 1) + 1) << 3) + chunk) * 8192, 8192, bar);
    };

    if (tid == 0) { issue(0, 0); issue(1, 1); }

    #pragma unroll
    for (int c = 0; c < 8; c++) {
        const int st = c % 3;
        bar_wait(barB + (st << 3), (c / 3) & 1);
        __syncthreads();
        if (c + 2 < 8 && tid == 0) issue(c + 2, (c + 2) % 3);

        const uint32_t stb = sb + st * FAT_STAGE;
        const uint32_t bbase = stb + 16384 + (bimg << 13);
        #pragma unroll
        for (int t = 0; t < 4; t++) {
            float (*ab)[4][4] = acc[t & 1];    // alternate banks per t-step
            uint32_t ah[4][4], bh[4][2];
            #pragma unroll
            for (int mi = 0; mi < 4; mi++) {
                const int row = a_row + (mi << 4);
                const uint32_t so = SWZ((row << 7) + (((t << 1) + a_kh) << 4));
                ldsm4(ah[mi][0], ah[mi][1], ah[mi][2], ah[mi][3], stb + so);
            }
            #pragma unroll
            for (int pr = 0; pr < 2; pr++) {
                const int row = b_lrow0 + (pr << 4);
                const uint32_t so = SWZ((row << 7) + (((t << 1) + b_kh) << 4));
                ldsm4(bh[2 * pr][0], bh[2 * pr][1], bh[2 * pr + 1][0], bh[2 * pr + 1][1],
                      bbase + so);
            }
            #pragma unroll
            for (int mi = 0; mi < 4; mi++)
                #pragma unroll
                for (int ni = 0; ni < 4; ni++)
                    mma_f16(ab[mi][ni], ah[mi], bh[ni]);
        }
    }

    #pragma unroll
    for (int mi = 0; mi < 4; mi++) {
        const int row = m0 + (wm << 6) + (mi << 4) + (lane >> 2);
        #pragma unroll
        for (int ni = 0; ni < 4; ni++) {
            const int col = n0 + (wn << 5) + (ni << 3) + ((lane & 3) << 1);
            const float b0 = __ldg(bias + col), b1 = __ldg(bias + col + 1);
            const float v0 = acc[0][mi][ni][0] + acc[1][mi][ni][0] + b0;
            const float v1 = acc[0][mi][ni][1] + acc[1][mi][ni][1] + b1;
            const float v2 = acc[0][mi][ni][2] + acc[1][mi][ni][2] + b0;
            const float v3 = acc[0][mi][ni][3] + acc[1][mi][ni][3] + b1;
            if constexpr (sizeof(OutT) == 4) {
                float2 o0 = {v0, v1}, o1 = {v2, v3};
                *(float2*)((float*)C + (size_t)row * DMODEL + col)       = o0;
                *(float2*)((float*)C + (size_t)(row + 8) * DMODEL + col) = o1;
            } else {
                __half2 o0 = __floats2half2_rn(v0, v1);
                __half2 o1 = __floats2half2_rn(v2, v3);
                *(__half2*)((__half*)C + (size_t)row * DMODEL + col)       = o0;
                *(__half2*)((__half*)C + (size_t)(row + 8) * DMODEL + col) = o1;
            }
        }
    }
}

// ---------------- slim GEMM: CTA tile 128x64, DOUBLE-BANKED accumulators -----
#define KCHUNKS 4
#define STAGE_BYTES 49152
#define GSMEM_TOTAL (2 * STAGE_BYTES + 64)

template <typename OutT>
__global__ __launch_bounds__(256, 2)
void gemm_bulk_f16(GemmPtrs p)
{
    extern __shared__ char smem[];
    const uint32_t sb = s2u(smem);
    const uint32_t barB = sb + 2 * STAGE_BYTES;
    const int z = blockIdx.z;
    const char* __restrict__ Ap = p.Ap[z];
    const char* __restrict__ Bp = p.Bp[z];
    const float* __restrict__ bias = p.bias[z];
    OutT* __restrict__ C = (OutT*)p.C[z];

    const int tid = threadIdx.x, wid = tid >> 5, lane = tid & 31;
    const int mblk = blockIdx.y, nblk = blockIdx.x;
    const int m0 = mblk << 7, n0 = nblk << 6;
    const int wm = wid & 3, wn = wid >> 2;

    const int a_row  = (wm << 5) + (lane & 15);
    const int a_kh   = lane >> 4;
    const int b_row0 = (wn << 5) + (((lane >> 4) & 1) << 3) + (lane & 7);
    const int b_kh   = (lane >> 3) & 1;

    float acc[2][2][4][4];    // [bank][mi][ni][r]
    #pragma unroll
    for (int bk = 0; bk < 2; bk++)
        #pragma unroll
        for (int i = 0; i < 2; i++)
            #pragma unroll
            for (int j = 0; j < 4; j++)
                #pragma unroll
                for (int r = 0; r < 4; r++) acc[bk][i][j][r] = 0.f;

    if (tid == 0) {
        bar_init(barB, 1);
        bar_init(barB + 8, 1);
        asm volatile("fence.proxy.async.shared::cta;" ::: "memory");
    }
    __syncthreads();

    auto issue = [&](int chunk, int st) {
        const uint32_t bar = barB + (st << 3);
        bar_expect_tx(bar, STAGE_BYTES);
        bulk_g2s(sb + st * STAGE_BYTES,
                 Ap + (((size_t)mblk << 3) + (chunk << 1)) * 16384, 32768, bar);
        bulk_g2s(sb + st * STAGE_BYTES + 32768,
                 Bp + (((size_t)nblk << 3) + (chunk << 1)) * 8192, 16384, bar);
    };

    if (tid == 0) { issue(0, 0); issue(1, 1); }

    #pragma unroll
    for (int c = 0; c < KCHUNKS; c++) {
        bar_wait(barB + ((c & 1) << 3), (c >> 1) & 1);
        __syncthreads();
        if (c >= 1 && c + 1 < KCHUNKS && tid == 0) issue(c + 1, (c + 1) & 1);

        const uint32_t stb = sb + (c & 1) * STAGE_BYTES;
        #pragma unroll
        for (int t = 0; t < 8; t++) {
            const int s = t >> 2, tt = t & 3;
            const uint32_t abase = stb + s * 16384;
            const uint32_t bbase = stb + 32768 + s * 8192;
            float (*ab)[4][4] = acc[t & 1];    // alternate banks per t-step
            uint32_t ah[2][4], bh[4][2];
            #pragma unroll
            for (int mi = 0; mi < 2; mi++) {
                const int row = a_row + (mi << 4);
                const uint32_t so = SWZ((row << 7) + (((tt << 1) + a_kh) << 4));
                ldsm4(ah[mi][0], ah[mi][1], ah[mi][2], ah[mi][3], abase + so);
            }
            #pragma unroll
            for (int pr = 0; pr < 2; pr++) {
                const int row = b_row0 + (pr << 4);
                const uint32_t so = SWZ((row << 7) + (((tt << 1) + b_kh) << 4));
                ldsm4(bh[2 * pr][0], bh[2 * pr][1], bh[2 * pr + 1][0], bh[2 * pr + 1][1],
                      bbase + so);
            }
            #pragma unroll
            for (int mi = 0; mi < 2; mi++)
                #pragma unroll
                for (int ni = 0; ni < 4; ni++)
                    mma_f16(ab[mi][ni], ah[mi], bh[ni]);
        }
    }

    #pragma unroll
    for (int mi = 0; mi < 2; mi++) {
        const int row = m0 + (wm << 5) + (mi << 4) + (lane >> 2);
        #pragma unroll
        for (int ni = 0; ni < 4; ni++) {
            const int col = n0 + (wn << 5) + (ni << 3) + ((lane & 3) << 1);
            const float b0 = __ldg(bias + col), b1 = __ldg(bias + col + 1);
            const float v0 = acc[0][mi][ni][0] + acc[1][mi][ni][0] + b0;
            const float v1 = acc[0][mi][ni][1] + acc[1][mi][ni][1] + b1;
            const float v2 = acc[0][mi][ni][2] + acc[1][mi][ni][2] + b0;
            const float v3 = acc[0][mi][ni][3] + acc[1][mi][ni][3] + b1;
            if constexpr (sizeof(OutT) == 4) {
                float2 o0 = {v0, v1}, o1 = {v2, v3};
                *(float2*)((float*)C + (size_t)row * DMODEL + col)       = o0;
                *(float2*)((float*)C + (size_t)(row + 8) * DMODEL + col) = o1;
            } else {
                __half2 o0 = __floats2half2_rn(v0, v1);
                __half2 o1 = __floats2half2_rn(v2, v3);
                *(__half2*)((__half*)C + (size_t)row * DMODEL + col)       = o0;
                *(__half2*)((__half*)C + (size_t)(row + 8) * DMODEL + col) = o1;
            }
        }
    }
}

// ---------------- fused preprocessing -> packed swizzled images --------------
__global__ __launch_bounds__(256)
void preprocess(const float* __restrict__ w0, const float* __restrict__ w1,
                const float* __restrict__ w2, const float* __restrict__ w3,
                const float* __restrict__ x0, const float* __restrict__ x1,
                const float* __restrict__ x2,
                char* __restrict__ Wp, char* __restrict__ Xp)
{
    const int bx = blockIdx.x, tid = threadIdx.x;
    if (bx < 1024) {
        __shared__ float t[32][33];
        const int z = bx >> 8, b = bx & 255;
        const float* __restrict__ W = (z == 0) ? w0 : (z == 1) ? w1 : (z == 2) ? w2 : w3;
        char* __restrict__ wp = Wp + (size_t)z * WPACK_Z;
        const int bxe = (b & 15) * 32, bye = (b >> 4) * 32;
        const int tx = tid & 31, ty = tid >> 5;
        #pragma unroll
        for (int j = 0; j < 32; j += 8)
            t[ty + j][tx] = W[(size_t)(bye + ty + j) * DMODEL + bxe + tx];
        __syncthreads();
        const int k = bye + tx;
        #pragma unroll
        for (int j = 0; j < 32; j += 8) {
            const int n = bxe + ty + j;
            const __half h = __float2half(t[tx][ty + j]);
            const size_t off = (((size_t)(n >> 6) << 3) + (k >> 6)) * 8192
                             + SWZ(((n & 63) << 7) + ((k & 63) << 1));
            *(__half*)(wp + off) = h;
        }
    } else {
        const int idx = bx - 1024;
        const int z = idx >> 11;
        const int blk = idx & 2047;
        const float* __restrict__ X = (z == 0) ? x0 : (z == 1) ? x1 : x2;
        char* __restrict__ xp = Xp + (size_t)z * XPACK_Z;
        const int i = (blk * 256 + tid) << 2;
        const int row = i >> 9, col = i & 511;
        const float4 v = *(const float4*)(X + i);
        __half2 p0 = __floats2half2_rn(v.x, v.y);
        __half2 p1 = __floats2half2_rn(v.z, v.w);
        uint2 o = {*(uint32_t*)&p0, *(uint32_t*)&p1};
        const size_t base = (((size_t)(row >> 7) << 3) + (col >> 6)) * 16384;
        const uint32_t off = SWZ(((row & 127) << 7) + ((col & 63) << 1));
        *(uint2*)(xp + base + off) = o;
    }
}

// ---------------- attention + residual: fp16 in, packed-image fp16 out -------
__global__ __launch_bounds__(256, 8)
void attn_residual_h(const __half* __restrict__ q, const __half* __restrict__ k,
                     const __half* __restrict__ v, const float* __restrict__ xq,
                     char* __restrict__ Yp)
{
    __shared__ __half2 sk2[8][DK];
    __shared__ __half2 sv2[8][DK];
    const int warp = threadIdx.x >> 5;
    const int lane = threadIdx.x & 31;
    const int row  = blockIdx.x;
    const int base = row * DMODEL + warp * DK;

    sk2[warp][lane]      = __half2half2(k[base + lane]);
    sk2[warp][lane + 32] = __half2half2(k[base + lane + 32]);
    sv2[warp][lane]      = __half2half2(v[base + lane]);
    sv2[warp][lane + 32] = __half2half2(v[base + lane + 32]);
    const float SCL = 0.125f * 1.4426950408889634f;
    const __half2 a01 = __floats2half2_rn(__half2float(q[base + lane]) * SCL,
                                          __half2float(q[base + lane + 32]) * SCL);
    __syncwarp();

    float num0 = 0.f, num1 = 0.f, den0 = 0.f, den1 = 0.f;
    #pragma unroll
    for (int jc = 0; jc < 4; jc++) {
        __half2 np = __float2half2_rn(0.f);
        __half2 dp = __float2half2_rn(0.f);
        #pragma unroll
        for (int j16 = 0; j16 < 16; j16++) {
            const int j = (jc << 4) + j16;
            const __half2 e = h2exp2(__hmul2(a01, sk2[warp][j]));
            np = __hfma2(e, sv2[warp][j], np);
            dp = __hadd2(dp, e);
        }
        const float2 nf = __half22float2(np);
        const float2 df = __half22float2(dp);
        num0 += nf.x; num1 += nf.y;
        den0 += df.x; den1 += df.y;
    }
    const float y0 = xq[base + lane]      - __fdividef(num0, den0);
    const float y1 = xq[base + lane + 32] - __fdividef(num1, den1);

    const size_t blkbase = (((size_t)(row >> 7) << 3) + warp) * 16384;
    const uint32_t rbase = (row & 127) << 7;
    *(__half*)(Yp + blkbase + SWZ(rbase + (lane << 1)))        = __float2half(y0);
    *(__half*)(Yp + blkbase + SWZ(rbase + ((lane + 32) << 1))) = __float2half(y1);
}

// ---------------- launch ------------------------------------------------------
extern "C" void kernel_launch(void* const* d_in, const int* in_sizes, int n_in,
                              void* d_out, int out_size)
{
    const float* x_q = (const float*)d_in[0];
    const float* x_k = (const float*)d_in[1];
    const float* x_v = (const float*)d_in[2];
    const float* Wq = (const float*)d_in[3];
    const float* bq = (const float*)d_in[4];
    const float* Wk = (const float*)d_in[5];
    const float* bk = (const float*)d_in[6];
    const float* Wv = (const float*)d_in[7];
    const float* bv = (const float*)d_in[8];
    const float* Wo = (const float*)d_in[9];
    const float* bo = (const float*)d_in[10];
    float* out = (float*)d_out;

    cudaFuncSetAttribute(gemm_fat_f16<__half>, cudaFuncAttributeMaxDynamicSharedMemorySize,
                         FAT_GSMEM);
    cudaFuncSetAttribute(gemm_bulk_f16<float>, cudaFuncAttributeMaxDynamicSharedMemorySize,
                         GSMEM_TOTAL);

    char *xpack, *wpack, *ypack;
    __half* qkv;
    cudaGetSymbolAddress((void**)&xpack, g_xpack);
    cudaGetSymbolAddress((void**)&wpack, g_wpack);
    cudaGetSymbolAddress((void**)&ypack, g_ypack);
    cudaGetSymbolAddress((void**)&qkv, g_qkv);

    // 1) preprocessing into packed swizzled tile images
    preprocess<<<1024 + 3 * (ND / 1024), 256>>>(Wq, Wk, Wv, Wo, x_q, x_k, x_v, wpack, xpack);

    // 2) Q/K/V projection GEMMs: fat 128x128 tiles, double-banked acc
    GemmPtrs pq;
    for (int z = 0; z < 3; z++) {
        pq.Ap[z] = xpack + (size_t)z * XPACK_Z;
        pq.Bp[z] = wpack + (size_t)z * WPACK_Z;
        pq.C[z]  = qkv + (size_t)z * ND;
    }
    pq.bias[0] = bq; pq.bias[1] = bk; pq.bias[2] = bv;
    gemm_fat_f16<__half><<<dim3(4, 32, 3), 256, FAT_GSMEM>>>(pq);

    // 3) attention + residual -> packed Y images
    attn_residual_h<<<NROWS, 256>>>(qkv, qkv + ND, qkv + 2 * (size_t)ND, x_q, ypack);

    // 4) output projection (slim 128x64 tiles, double-banked acc), fp32 out
    GemmPtrs po;
    po.Ap[0] = ypack;
    po.Bp[0] = wpack + 3 * (size_t)WPACK_Z;
    po.bias[0] = bo;
    po.C[0] = out;
    po.Ap[1] = po.Ap[2] = po.Ap[0];
    po.Bp[1] = po.Bp[2] = po.Bp[0];
    po.bias[1] = po.bias[2] = bo;
    po.C[1] = po.C[2] = po.C[0];
    gemm_bulk_f16<float><<<dim3(8, 32, 1), 256, GSMEM_TOTAL>>>(po);
}

// round 16
// speedup vs baseline: 1.0630x; 1.0630x over previous
#include <cuda_runtime.h>
#include <cuda_fp16.h>
#include <cstdint>

#define NROWS  4096
#define DMODEL 512
#define DK     64
#define ND     (NROWS * DMODEL)
#define DD     (DMODEL * DMODEL)

// Packed, pre-swizzled tile images (exact smem layout, bulk-TMA contiguous):
//  X pack: [z][mblk(32)][chunk(8)] -> 128 rows x 128B image (16KB)
//  W pack: [z][nblk(8)][chunk(8)]  -> 64 rows x 128B image  (8KB)
//  Y pack: [mblk(32)][chunk(8)]    -> 16KB images (attention output)
#define XPACK_Z (32 * 8 * 16384)
#define WPACK_Z (8 * 8 * 8192)

__device__ __align__(128) char  g_xpack[3 * XPACK_Z];
__device__ __align__(128) char  g_wpack[4 * WPACK_Z];
__device__ __align__(128) char  g_ypack[XPACK_Z];
__device__ __half g_qkv[3][ND];          // fp16 Q/K/V (plain row-major)

// ---------------- PTX helpers ----------------
static __device__ __forceinline__ uint32_t s2u(const void* p) {
    uint32_t a;
    asm("{ .reg .u64 t; cvta.to.shared.u64 t, %1; cvt.u32.u64 %0, t; }" : "=r"(a) : "l"(p));
    return a;
}
static __device__ __forceinline__ void ldsm4(uint32_t& r0, uint32_t& r1, uint32_t& r2,
                                             uint32_t& r3, uint32_t a) {
    asm volatile("ldmatrix.sync.aligned.m8n8.x4.shared.b16 {%0,%1,%2,%3}, [%4];"
                 : "=r"(r0), "=r"(r1), "=r"(r2), "=r"(r3) : "r"(a));
}
static __device__ __forceinline__ void mma_f16(float* c, const uint32_t* a, const uint32_t* b) {
    asm volatile(
        "mma.sync.aligned.m16n8k16.row.col.f32.f16.f16.f32 "
        "{%0,%1,%2,%3}, {%4,%5,%6,%7}, {%8,%9}, {%0,%1,%2,%3};"
        : "+f"(c[0]), "+f"(c[1]), "+f"(c[2]), "+f"(c[3])
        : "r"(a[0]), "r"(a[1]), "r"(a[2]), "r"(a[3]), "r"(b[0]), "r"(b[1]));
}
static __device__ __forceinline__ void bar_init(uint32_t a, uint32_t c) {
    asm volatile("mbarrier.init.shared.b64 [%0], %1;" :: "r"(a), "r"(c) : "memory");
}
static __device__ __forceinline__ void bar_expect_tx(uint32_t a, uint32_t tx) {
    asm volatile("mbarrier.arrive.expect_tx.shared.b64 _, [%0], %1;" :: "r"(a), "r"(tx) : "memory");
}
static __device__ __forceinline__ void bulk_g2s(uint32_t dst, const void* src,
                                                uint32_t bytes, uint32_t bar) {
    asm volatile(
        "cp.async.bulk.shared::cluster.global.mbarrier::complete_tx::bytes [%0], [%1], %2, [%3];"
        :: "r"(dst), "l"(src), "r"(bytes), "r"(bar) : "memory");
}
static __device__ __forceinline__ void bar_wait(uint32_t a, uint32_t parity) {
    uint32_t done;
    asm volatile(
        "{\n\t.reg .pred p;\n\t"
        "mbarrier.try_wait.parity.acquire.cta.shared::cta.b64 p, [%1], %2;\n\t"
        "selp.b32 %0, 1, 0, p;\n\t}"
        : "=r"(done) : "r"(a), "r"(parity) : "memory");
    if (!done) {
        asm volatile(
            "{\n\t.reg .pred P1;\n\t"
            "WL_%=:\n\t"
            "mbarrier.try_wait.parity.acquire.cta.shared::cta.b64 P1, [%0], %1, 0x989680;\n\t"
            "@P1 bra.uni WD_%=;\n\t"
            "bra.uni WL_%=;\n\t"
            "WD_%=:\n\t}"
            :: "r"(a), "r"(parity) : "memory");
    }
}
#define SWZ(x) ((x) ^ (((x) >> 3) & 0x70))

struct GemmPtrs {
    const char*  Ap[3];
    const char*  Bp[3];
    const float* bias[3];
    void*        C[3];
};

// ---------------- FAT GEMM: CTA tile 128x128 (single-banked acc, R14 form) ---
// 8 warps as 2m x 4n, warp tile 64x32. K=512 in 8 chunks of 64.
// Stage = A 16KB + B 2x8KB = 32KB; 3-slot mbarrier pipeline; <=2 CTAs/SM.
// Used for QKV (384 CTAs, 1.3 waves) AND O (128 CTAs = one balanced 1/SM wave).
#define FAT_STAGE 32768
#define FAT_GSMEM (3 * FAT_STAGE + 64)

template <typename OutT>
__global__ __launch_bounds__(256, 2)
void gemm_fat_f16(GemmPtrs p)
{
    extern __shared__ char smem[];
    const uint32_t sb = s2u(smem);
    const uint32_t barB = sb + 3 * FAT_STAGE;
    const int z = blockIdx.z;
    const char* __restrict__ Ap = p.Ap[z];
    const char* __restrict__ Bp = p.Bp[z];
    const float* __restrict__ bias = p.bias[z];
    OutT* __restrict__ C = (OutT*)p.C[z];

    const int tid = threadIdx.x, wid = tid >> 5, lane = tid & 31;
    const int mblk = blockIdx.y, jn = blockIdx.x;
    const int m0 = mblk << 7, n0 = jn << 7;
    const int wm = wid & 1, wn = wid >> 1;

    const int a_row   = (wm << 6) + (lane & 15);
    const int a_kh    = lane >> 4;
    const int b_lrow0 = ((wn & 1) << 5) + (((lane >> 4) & 1) << 3) + (lane & 7);
    const int b_kh    = (lane >> 3) & 1;
    const int bimg    = wn >> 1;

    float acc[4][4][4];
    #pragma unroll
    for (int i = 0; i < 4; i++)
        #pragma unroll
        for (int j = 0; j < 4; j++)
            #pragma unroll
            for (int r = 0; r < 4; r++) acc[i][j][r] = 0.f;

    if (tid == 0) {
        #pragma unroll
        for (int s = 0; s < 3; s++) bar_init(barB + (s << 3), 1);
        asm volatile("fence.proxy.async.shared::cta;" ::: "memory");
    }
    __syncthreads();

    auto issue = [&](int chunk, int st) {
        const uint32_t bar = barB + (st << 3);
        bar_expect_tx(bar, FAT_STAGE);
        bulk_g2s(sb + st * FAT_STAGE,
                 Ap + (((size_t)mblk << 3) + chunk) * 16384, 16384, bar);
        bulk_g2s(sb + st * FAT_STAGE + 16384,
                 Bp + ((((size_t)jn << 1) << 3) + chunk) * 8192, 8192, bar);
        bulk_g2s(sb + st * FAT_STAGE + 24576,
                 Bp + (((((size_t)jn << 1) + 1) << 3) + chunk) * 8192, 8192, bar);
    };

    if (tid == 0) { issue(0, 0); issue(1, 1); }

    #pragma unroll
    for (int c = 0; c < 8; c++) {
        const int st = c % 3;
        bar_wait(barB + (st << 3), (c / 3) & 1);
        __syncthreads();              // all warps finished compute(c-1): slot (c+2)%3 free
        if (c + 2 < 8 && tid == 0) issue(c + 2, (c + 2) % 3);

        const uint32_t stb = sb + st * FAT_STAGE;
        const uint32_t bbase = stb + 16384 + (bimg << 13);
        #pragma unroll
        for (int t = 0; t < 4; t++) {
            uint32_t ah[4][4], bh[4][2];
            #pragma unroll
            for (int mi = 0; mi < 4; mi++) {
                const int row = a_row + (mi << 4);
                const uint32_t so = SWZ((row << 7) + (((t << 1) + a_kh) << 4));
                ldsm4(ah[mi][0], ah[mi][1], ah[mi][2], ah[mi][3], stb + so);
            }
            #pragma unroll
            for (int pr = 0; pr < 2; pr++) {
                const int row = b_lrow0 + (pr << 4);
                const uint32_t so = SWZ((row << 7) + (((t << 1) + b_kh) << 4));
                ldsm4(bh[2 * pr][0], bh[2 * pr][1], bh[2 * pr + 1][0], bh[2 * pr + 1][1],
                      bbase + so);
            }
            #pragma unroll
            for (int mi = 0; mi < 4; mi++)
                #pragma unroll
                for (int ni = 0; ni < 4; ni++)
                    mma_f16(acc[mi][ni], ah[mi], bh[ni]);
        }
    }

    #pragma unroll
    for (int mi = 0; mi < 4; mi++) {
        const int row = m0 + (wm << 6) + (mi << 4) + (lane >> 2);
        #pragma unroll
        for (int ni = 0; ni < 4; ni++) {
            const int col = n0 + (wn << 5) + (ni << 3) + ((lane & 3) << 1);
            const float b0 = __ldg(bias + col), b1 = __ldg(bias + col + 1);
            if constexpr (sizeof(OutT) == 4) {
                float2 o0 = {acc[mi][ni][0] + b0, acc[mi][ni][1] + b1};
                float2 o1 = {acc[mi][ni][2] + b0, acc[mi][ni][3] + b1};
                *(float2*)((float*)C + (size_t)row * DMODEL + col)       = o0;
                *(float2*)((float*)C + (size_t)(row + 8) * DMODEL + col) = o1;
            } else {
                __half2 o0 = __floats2half2_rn(acc[mi][ni][0] + b0, acc[mi][ni][1] + b1);
                __half2 o1 = __floats2half2_rn(acc[mi][ni][2] + b0, acc[mi][ni][3] + b1);
                *(__half2*)((__half*)C + (size_t)row * DMODEL + col)       = o0;
                *(__half2*)((__half*)C + (size_t)(row + 8) * DMODEL + col) = o1;
            }
        }
    }
}

// ---------------- fused preprocessing -> packed swizzled images --------------
__global__ __launch_bounds__(256)
void preprocess(const float* __restrict__ w0, const float* __restrict__ w1,
                const float* __restrict__ w2, const float* __restrict__ w3,
                const float* __restrict__ x0, const float* __restrict__ x1,
                const float* __restrict__ x2,
                char* __restrict__ Wp, char* __restrict__ Xp)
{
    const int bx = blockIdx.x, tid = threadIdx.x;
    if (bx < 1024) {
        __shared__ float t[32][33];
        const int z = bx >> 8, b = bx & 255;
        const float* __restrict__ W = (z == 0) ? w0 : (z == 1) ? w1 : (z == 2) ? w2 : w3;
        char* __restrict__ wp = Wp + (size_t)z * WPACK_Z;
        const int bxe = (b & 15) * 32, bye = (b >> 4) * 32;
        const int tx = tid & 31, ty = tid >> 5;
        #pragma unroll
        for (int j = 0; j < 32; j += 8)
            t[ty + j][tx] = W[(size_t)(bye + ty + j) * DMODEL + bxe + tx];
        __syncthreads();
        const int k = bye + tx;
        #pragma unroll
        for (int j = 0; j < 32; j += 8) {
            const int n = bxe + ty + j;
            const __half h = __float2half(t[tx][ty + j]);
            const size_t off = (((size_t)(n >> 6) << 3) + (k >> 6)) * 8192
                             + SWZ(((n & 63) << 7) + ((k & 63) << 1));
            *(__half*)(wp + off) = h;
        }
    } else {
        const int idx = bx - 1024;
        const int z = idx >> 11;
        const int blk = idx & 2047;
        const float* __restrict__ X = (z == 0) ? x0 : (z == 1) ? x1 : x2;
        char* __restrict__ xp = Xp + (size_t)z * XPACK_Z;
        const int i = (blk * 256 + tid) << 2;
        const int row = i >> 9, col = i & 511;
        const float4 v = *(const float4*)(X + i);
        __half2 p0 = __floats2half2_rn(v.x, v.y);
        __half2 p1 = __floats2half2_rn(v.z, v.w);
        uint2 o = {*(uint32_t*)&p0, *(uint32_t*)&p1};
        const size_t base = (((size_t)(row >> 7) << 3) + (col >> 6)) * 16384;
        const uint32_t off = SWZ(((row & 127) << 7) + ((col & 63) << 1));
        *(uint2*)(xp + base + off) = o;
    }
}

// ---------------- attention + residual: fp16 in, packed-image fp16 out -------
__global__ __launch_bounds__(256, 8)
void attn_residual_h(const __half* __restrict__ q, const __half* __restrict__ k,
                     const __half* __restrict__ v, const float* __restrict__ xq,
                     char* __restrict__ Yp)
{
    __shared__ __half2 sk2[8][DK];
    __shared__ __half2 sv2[8][DK];
    const int warp = threadIdx.x >> 5;
    const int lane = threadIdx.x & 31;
    const int row  = blockIdx.x;
    const int base = row * DMODEL + warp * DK;

    sk2[warp][lane]      = __half2half2(k[base + lane]);
    sk2[warp][lane + 32] = __half2half2(k[base + lane + 32]);
    sv2[warp][lane]      = __half2half2(v[base + lane]);
    sv2[warp][lane + 32] = __half2half2(v[base + lane + 32]);
    const float SCL = 0.125f * 1.4426950408889634f;
    const __half2 a01 = __floats2half2_rn(__half2float(q[base + lane]) * SCL,
                                          __half2float(q[base + lane + 32]) * SCL);
    __syncwarp();

    float num0 = 0.f, num1 = 0.f, den0 = 0.f, den1 = 0.f;
    #pragma unroll
    for (int jc = 0; jc < 4; jc++) {
        __half2 np = __float2half2_rn(0.f);
        __half2 dp = __float2half2_rn(0.f);
        #pragma unroll
        for (int j16 = 0; j16 < 16; j16++) {
            const int j = (jc << 4) + j16;
            const __half2 e = h2exp2(__hmul2(a01, sk2[warp][j]));
            np = __hfma2(e, sv2[warp][j], np);
            dp = __hadd2(dp, e);
        }
        const float2 nf = __half22float2(np);
        const float2 df = __half22float2(dp);
        num0 += nf.x; num1 += nf.y;
        den0 += df.x; den1 += df.y;
    }
    const float y0 = xq[base + lane]      - __fdividef(num0, den0);
    const float y1 = xq[base + lane + 32] - __fdividef(num1, den1);

    const size_t blkbase = (((size_t)(row >> 7) << 3) + warp) * 16384;
    const uint32_t rbase = (row & 127) << 7;
    *(__half*)(Yp + blkbase + SWZ(rbase + (lane << 1)))        = __float2half(y0);
    *(__half*)(Yp + blkbase + SWZ(rbase + ((lane + 32) << 1))) = __float2half(y1);
}

// ---------------- launch ------------------------------------------------------
extern "C" void kernel_launch(void* const* d_in, const int* in_sizes, int n_in,
                              void* d_out, int out_size)
{
    const float* x_q = (const float*)d_in[0];
    const float* x_k = (const float*)d_in[1];
    const float* x_v = (const float*)d_in[2];
    const float* Wq = (const float*)d_in[3];
    const float* bq = (const float*)d_in[4];
    const float* Wk = (const float*)d_in[5];
    const float* bk = (const float*)d_in[6];
    const float* Wv = (const float*)d_in[7];
    const float* bv = (const float*)d_in[8];
    const float* Wo = (const float*)d_in[9];
    const float* bo = (const float*)d_in[10];
    float* out = (float*)d_out;

    cudaFuncSetAttribute(gemm_fat_f16<__half>, cudaFuncAttributeMaxDynamicSharedMemorySize,
                         FAT_GSMEM);
    cudaFuncSetAttribute(gemm_fat_f16<float>, cudaFuncAttributeMaxDynamicSharedMemorySize,
                         FAT_GSMEM);

    char *xpack, *wpack, *ypack;
    __half* qkv;
    cudaGetSymbolAddress((void**)&xpack, g_xpack);
    cudaGetSymbolAddress((void**)&wpack, g_wpack);
    cudaGetSymbolAddress((void**)&ypack, g_ypack);
    cudaGetSymbolAddress((void**)&qkv, g_qkv);

    // 1) preprocessing into packed swizzled tile images
    preprocess<<<1024 + 3 * (ND / 1024), 256>>>(Wq, Wk, Wv, Wo, x_q, x_k, x_v, wpack, xpack);

    // 2) Q/K/V projection GEMMs: fat 128x128 tiles (384 CTAs)
    GemmPtrs pq;
    for (int z = 0; z < 3; z++) {
        pq.Ap[z] = xpack + (size_t)z * XPACK_Z;
        pq.Bp[z] = wpack + (size_t)z * WPACK_Z;
        pq.C[z]  = qkv + (size_t)z * ND;
    }
    pq.bias[0] = bq; pq.bias[1] = bk; pq.bias[2] = bv;
    gemm_fat_f16<__half><<<dim3(4, 32, 3), 256, FAT_GSMEM>>>(pq);

    // 3) attention + residual -> packed Y images
    attn_residual_h<<<NROWS, 256>>>(qkv, qkv + ND, qkv + 2 * (size_t)ND, x_q, ypack);

    // 4) output projection: fat 128x128 tiles -> 128 CTAs = one balanced
    //    1-CTA/SM wave (fixes the 108-SMs-do-2x load imbalance of 256 slim CTAs)
    GemmPtrs po;
    po.Ap[0] = ypack;
    po.Bp[0] = wpack + 3 * (size_t)WPACK_Z;
    po.bias[0] = bo;
    po.C[0] = out;
    po.Ap[1] = po.Ap[2] = po.Ap[0];
    po.Bp[1] = po.Bp[2] = po.Bp[0];
    po.bias[1] = po.bias[2] = bo;
    po.C[1] = po.C[2] = po.C[0];
    gemm_fat_f16<float><<<dim3(4, 32, 1), 256, FAT_GSMEM>>>(po);
}